// round 16
// baseline (speedup 1.0000x reference)
#include <cuda_runtime.h>
#include <cuda_bf16.h>
#include <stdint.h>

// RBF logits: out[b,c] = 2*dot(x[b],w[c]) - ||x[b]||^2 - ||w[c]||^2
// B=32768, C=4096, D=64. CTA tile 128x128 as two 64-col halves (3 CTAs/SM),
// fragment loads via ldmatrix.x4 (4x fewer L1 instructions + address math),
// epilogue staged in conflict-free smem, cp.async.bulk out, half-0 drain
// overlaps half-1 MMA.  (R12 fix: tile-load loop covers all 128 rows.)

#define BM 128
#define BN 128
#define KD 64
#define PAD 72      // bf16 elems per tile row (144B): conflict-free LDSM
#define SS  72      // floats per stage row (288B): mod32==8 -> conflict-free STS.v2

// dynamic smem (bytes):
//   [0, 36864)       Xs (128x72 bf16) + Ws (128x72 bf16);  STAGE1 reuses this
//   [36864, 73728)   STAGE0 (128 rows x 288B)
//   [73728, 74752)   xsq / wsq (128 f32 each)
#define OFF_XS   0u
#define OFF_WS   18432u
#define STAGE1   0u
#define STAGE0   36864u
#define OFF_XSQ  73728u
#define OFF_WSQ  74240u
#define SMEM_BYTES 74752u

static __device__ __forceinline__ uint32_t pack_bf16(float a, float b) {
    __nv_bfloat162 h = __floats2bfloat162_rn(a, b);
    return *reinterpret_cast<uint32_t*>(&h);
}
static __device__ __forceinline__ void sts128u(uint32_t addr, uint32_t a, uint32_t b,
                                               uint32_t c, uint32_t d) {
    asm volatile("st.shared.v4.b32 [%0], {%1,%2,%3,%4};"
                 :: "r"(addr), "r"(a), "r"(b), "r"(c), "r"(d));
}
static __device__ __forceinline__ void sts64f(uint32_t addr, float a, float b) {
    asm volatile("st.shared.v2.f32 [%0], {%1,%2};" :: "r"(addr), "f"(a), "f"(b));
}
static __device__ __forceinline__ void ldsm_x4(uint32_t addr, uint32_t& r0, uint32_t& r1,
                                               uint32_t& r2, uint32_t& r3) {
    asm volatile("ldmatrix.sync.aligned.m8n8.x4.shared.b16 {%0,%1,%2,%3}, [%4];"
                 : "=r"(r0), "=r"(r1), "=r"(r2), "=r"(r3) : "r"(addr));
}

__global__ __launch_bounds__(256, 3)
void rbf_logits_kernel(const float* __restrict__ x,
                       const float* __restrict__ w,
                       float* __restrict__ out,
                       int C) {
    extern __shared__ __align__(16) char smem[];
    const uint32_t sb = (uint32_t)__cvta_generic_to_shared(smem);
    float* xsq_s = reinterpret_cast<float*>(smem + OFF_XSQ);
    float* wsq_s = reinterpret_cast<float*>(smem + OFF_WSQ);

    const int tid  = threadIdx.x;
    const int lane = tid & 31;
    const int wid  = tid >> 5;
    const int row0 = blockIdx.y * BM;
    const int col0 = blockIdx.x * BN;

    // ---- Load X/W tiles -> bf16 smem (16B stores) + fused sum-of-squares ----
    // Thread handles 8 consecutive floats (2 float4); 8 threads per 64-f row.
    // 128 rows x 8 slots = 1024 thread-slots = 4 iterations of 256 threads.
    {
        const float4* g = reinterpret_cast<const float4*>(x + (size_t)row0 * KD);
        #pragma unroll
        for (int i = 0; i < 4; i++) {
            int idx = tid + i * 256;              // 0..1023 ; 8 per row
            int r = idx >> 3, p = idx & 7;
            float4 v0 = g[idx * 2];
            float4 v1 = g[idx * 2 + 1];
            float ss = v0.x*v0.x + v0.y*v0.y + v0.z*v0.z + v0.w*v0.w
                     + v1.x*v1.x + v1.y*v1.y + v1.z*v1.z + v1.w*v1.w;
            sts128u(sb + OFF_XS + (uint32_t)(r * PAD + p * 8) * 2u,
                    pack_bf16(v0.x, v0.y), pack_bf16(v0.z, v0.w),
                    pack_bf16(v1.x, v1.y), pack_bf16(v1.z, v1.w));
            #pragma unroll
            for (int d = 4; d >= 1; d >>= 1) ss += __shfl_xor_sync(0xffffffffu, ss, d);
            if ((tid & 7) == 0) xsq_s[r] = ss;
        }
    }
    {
        const float4* g = reinterpret_cast<const float4*>(w + (size_t)col0 * KD);
        #pragma unroll
        for (int i = 0; i < 4; i++) {
            int idx = tid + i * 256;
            int r = idx >> 3, p = idx & 7;
            float4 v0 = g[idx * 2];
            float4 v1 = g[idx * 2 + 1];
            float ss = v0.x*v0.x + v0.y*v0.y + v0.z*v0.z + v0.w*v0.w
                     + v1.x*v1.x + v1.y*v1.y + v1.z*v1.z + v1.w*v1.w;
            sts128u(sb + OFF_WS + (uint32_t)(r * PAD + p * 8) * 2u,
                    pack_bf16(v0.x, v0.y), pack_bf16(v0.z, v0.w),
                    pack_bf16(v1.x, v1.y), pack_bf16(v1.z, v1.w));
            #pragma unroll
            for (int d = 4; d >= 1; d >>= 1) ss += __shfl_xor_sync(0xffffffffu, ss, d);
            if ((tid & 7) == 0) wsq_s[r] = ss;
        }
    }
    __syncthreads();

    // ---- Warp tiling per half: 8 warps as 2(M) x 4(N); warp = 64 x 16 ----
    const int warp_m = wid >> 2;
    const int warp_n = wid & 3;
    const int m_base = warp_m * 64;
    const int lr = lane >> 2;   // 0..7
    const int lq = lane & 3;    // 0..3

    // ldmatrix lane addressing (precomputed once):
    //   mat = lane>>3 (0..3), r = lane&7
    // A x4 per (mi,k): mats = {rows+0,klo},{rows+8,klo},{rows+0,khi},{rows+8,khi}
    const int a_mat = lane >> 3, a_r = lane & 7;
    const uint32_t a_base = sb + OFF_XS +
        (uint32_t)(((m_base + ((a_mat & 1) << 3) + a_r) * PAD + ((a_mat >> 1) << 3)) * 2);
    // B x4 per k (both ni): mats = {ni0,klo},{ni0,khi},{ni1,klo},{ni1,khi}
    const uint32_t b_row_part = (uint32_t)((((a_mat >> 1) << 3) + a_r) * PAD * 2);
    const uint32_t b_col_part = (uint32_t)(((a_mat & 1) << 3) * 2);

    #pragma unroll
    for (int h = 0; h < 2; h++) {
        const int n_base = h * 64 + warp_n * 16;
        const uint32_t b_base = sb + OFF_WS + (uint32_t)(n_base * PAD * 2)
                              + b_row_part + b_col_part;

        float acc[4][2][4];
        #pragma unroll
        for (int mi = 0; mi < 4; mi++)
            #pragma unroll
            for (int ni = 0; ni < 2; ni++)
                #pragma unroll
                for (int e = 0; e < 4; e++)
                    acc[mi][ni][e] = 0.f;

        #pragma unroll
        for (int k0 = 0; k0 < KD; k0 += 16) {
            uint32_t afrag[4][4];
            #pragma unroll
            for (int mi = 0; mi < 4; mi++)
                ldsm_x4(a_base + (uint32_t)(mi * 16 * PAD * 2 + k0 * 2),
                        afrag[mi][0], afrag[mi][1], afrag[mi][2], afrag[mi][3]);
            uint32_t bfrag[4];   // [ni0 lo, ni0 hi, ni1 lo, ni1 hi]
            ldsm_x4(b_base + (uint32_t)(k0 * 2),
                    bfrag[0], bfrag[1], bfrag[2], bfrag[3]);
            #pragma unroll
            for (int mi = 0; mi < 4; mi++) {
                #pragma unroll
                for (int ni = 0; ni < 2; ni++) {
                    asm volatile(
                        "mma.sync.aligned.m16n8k16.row.col.f32.bf16.bf16.f32 "
                        "{%0,%1,%2,%3}, {%4,%5,%6,%7}, {%8,%9}, {%0,%1,%2,%3};\n"
                        : "+f"(acc[mi][ni][0]), "+f"(acc[mi][ni][1]),
                          "+f"(acc[mi][ni][2]), "+f"(acc[mi][ni][3])
                        : "r"(afrag[mi][0]), "r"(afrag[mi][1]),
                          "r"(afrag[mi][2]), "r"(afrag[mi][3]),
                          "r"(bfrag[ni * 2]), "r"(bfrag[ni * 2 + 1]));
                }
            }
        }

        const uint32_t stage = (h == 0) ? (sb + STAGE0) : (sb + STAGE1);
        // Half-1 stage overwrites the tiles: wait until all frag reads done.
        if (h == 1) __syncthreads();

        // ---- Epilogue: 2*acc - xsq - wsq into conflict-free stage ----
        #pragma unroll
        for (int mi = 0; mi < 4; mi++) {
            int rl0 = m_base + mi * 16 + lr;
            float xs0 = xsq_s[rl0];
            float xs1 = xsq_s[rl0 + 8];
            #pragma unroll
            for (int ni = 0; ni < 2; ni++) {
                int cg = n_base + ni * 8 + lq * 2;     // tile-global col
                int cl = cg - h * 64;                  // col within half
                float ws0 = wsq_s[cg];
                float ws1 = wsq_s[cg + 1];
                sts64f(stage + (uint32_t)(rl0 * SS + cl) * 4u,
                       2.f * acc[mi][ni][0] - xs0 - ws0,
                       2.f * acc[mi][ni][1] - xs0 - ws1);
                sts64f(stage + (uint32_t)((rl0 + 8) * SS + cl) * 4u,
                       2.f * acc[mi][ni][2] - xs1 - ws0,
                       2.f * acc[mi][ni][3] - xs1 - ws1);
            }
        }
        asm volatile("fence.proxy.async.shared::cta;" ::: "memory");
        __syncthreads();

        // ---- Bulk stores: warp w, lanes 0-15 -> rows w*16+lane, 256B each ----
        if (lane < 16) {
            int r = wid * 16 + lane;
            const float* dst = out + (size_t)(row0 + r) * C + col0 + h * 64;
            uint32_t src = stage + (uint32_t)r * (SS * 4u);
            asm volatile("cp.async.bulk.global.shared::cta.bulk_group [%0], [%1], %2;"
                         :: "l"(dst), "r"(src), "r"(256u) : "memory");
            asm volatile("cp.async.bulk.commit_group;" ::: "memory");
        }
        // No wait for h==0: the drain overlaps the half-1 MMA.
    }

    // Drain all outstanding bulk stores before CTA exit.
    if (lane < 16)
        asm volatile("cp.async.bulk.wait_group 0;" ::: "memory");
}

extern "C" void kernel_launch(void* const* d_in, const int* in_sizes, int n_in,
                              void* d_out, int out_size) {
    const float* x = (const float*)d_in[0];
    const float* w = (const float*)d_in[1];
    float* out = (float*)d_out;
    int B = in_sizes[0] / KD;   // 32768
    int C = in_sizes[1] / KD;   // 4096

    cudaFuncSetAttribute(rbf_logits_kernel,
                         cudaFuncAttributeMaxDynamicSharedMemorySize, SMEM_BYTES);
    dim3 grid(C / BN, B / BM);  // (32, 256)
    rbf_logits_kernel<<<grid, 256, SMEM_BYTES>>>(x, w, out, C);
}

// round 17
// speedup vs baseline: 1.6152x; 1.6152x over previous
#include <cuda_runtime.h>
#include <cuda_bf16.h>
#include <stdint.h>

// RBF logits: out[b,c] = 2*dot(x[b],w[c]) - ||x[b]||^2 - ||w[c]||^2
// B=32768, C=4096, D=64. CTA tile 128x128 split along M into two 64-row
// halves (re-reads cheap B frags instead of expensive A frags: 128 vs 160
// frag LDS per warp). 32 acc regs -> 3 CTAs/SM. Manual LDS fragments (R16
// showed ldmatrix serialization loses). Epilogue staged in conflict-free
// smem then cp.async.bulk; half-0 drain overlaps half-1 MMA.

#define BM 128
#define BN 128
#define KD 64
#define PAD 72      // bf16 elems per tile row (144B): conflict-free frag LDS
#define SS  136     // floats per stage row (544B): mod128==32 -> conflict-free

// dynamic smem (bytes):
//   [0, 36864)       Xs (128x72 bf16) + Ws (128x72 bf16); STAGE1 reuses this
//   [36864, 71680)   STAGE0 (64 rows x 544B)
//   [71680, 72704)   xsq / wsq (128 f32 each)
#define OFF_XS   0u
#define OFF_WS   18432u
#define STAGE1   0u
#define STAGE0   36864u
#define OFF_XSQ  71680u
#define OFF_WSQ  72192u
#define SMEM_BYTES 72704u

static __device__ __forceinline__ uint32_t pack_bf16(float a, float b) {
    __nv_bfloat162 h = __floats2bfloat162_rn(a, b);
    return *reinterpret_cast<uint32_t*>(&h);
}
static __device__ __forceinline__ void sts64u(uint32_t addr, uint32_t a, uint32_t b) {
    asm volatile("st.shared.v2.b32 [%0], {%1,%2};" :: "r"(addr), "r"(a), "r"(b));
}
static __device__ __forceinline__ void sts64f(uint32_t addr, float a, float b) {
    asm volatile("st.shared.v2.f32 [%0], {%1,%2};" :: "r"(addr), "f"(a), "f"(b));
}

__global__ __launch_bounds__(256, 3)
void rbf_logits_kernel(const float* __restrict__ x,
                       const float* __restrict__ w,
                       float* __restrict__ out,
                       int C) {
    extern __shared__ __align__(16) char smem[];
    const uint32_t sb = (uint32_t)__cvta_generic_to_shared(smem);
    __nv_bfloat16* Xs = reinterpret_cast<__nv_bfloat16*>(smem + OFF_XS);
    __nv_bfloat16* Ws = reinterpret_cast<__nv_bfloat16*>(smem + OFF_WS);
    float* xsq_s = reinterpret_cast<float*>(smem + OFF_XSQ);
    float* wsq_s = reinterpret_cast<float*>(smem + OFF_WSQ);

    const int tid  = threadIdx.x;
    const int lane = tid & 31;
    const int wid  = tid >> 5;
    const int row0 = blockIdx.y * BM;
    const int col0 = blockIdx.x * BN;

    // ---- Load X/W tiles -> bf16 smem with fused sum-of-squares reduce ----
    // (R8-proven pattern: 1 float4 per thread per iter, fully coalesced.)
    {
        const float4* g = reinterpret_cast<const float4*>(x + (size_t)row0 * KD);
        #pragma unroll
        for (int i = 0; i < 8; i++) {
            int idx = tid + i * 256;          // float4 index; 16 per row
            int r = idx >> 4, c4 = idx & 15;
            float4 v = g[idx];
            float ss = v.x*v.x + v.y*v.y + v.z*v.z + v.w*v.w;
            sts64u(sb + OFF_XS + (uint32_t)(r * PAD + c4 * 4) * 2u,
                   pack_bf16(v.x, v.y), pack_bf16(v.z, v.w));
            #pragma unroll
            for (int d = 8; d >= 1; d >>= 1) ss += __shfl_xor_sync(0xffffffffu, ss, d);
            if ((tid & 15) == 0) xsq_s[r] = ss;
        }
    }
    {
        const float4* g = reinterpret_cast<const float4*>(w + (size_t)col0 * KD);
        #pragma unroll
        for (int i = 0; i < 8; i++) {
            int idx = tid + i * 256;
            int r = idx >> 4, c4 = idx & 15;
            float4 v = g[idx];
            float ss = v.x*v.x + v.y*v.y + v.z*v.z + v.w*v.w;
            sts64u(sb + OFF_WS + (uint32_t)(r * PAD + c4 * 4) * 2u,
                   pack_bf16(v.x, v.y), pack_bf16(v.z, v.w));
            #pragma unroll
            for (int d = 8; d >= 1; d >>= 1) ss += __shfl_xor_sync(0xffffffffu, ss, d);
            if ((tid & 15) == 0) wsq_s[r] = ss;
        }
    }
    __syncthreads();

    // ---- Per half (64 rows x 128 cols): 8 warps as 2(M) x 4(N), warp 32x32 ----
    const int warp_m = wid >> 2;     // 0..1
    const int warp_n = wid & 3;      // 0..3
    const int n_base = warp_n * 32;  // same cols both halves (B re-read, cheap)
    const int lr = lane >> 2;        // 0..7
    const int lq = lane & 3;         // 0..3

    #pragma unroll
    for (int h = 0; h < 2; h++) {
        const int m_base = h * 64 + warp_m * 32;   // tile-global row base

        float acc[2][4][4];
        #pragma unroll
        for (int mi = 0; mi < 2; mi++)
            #pragma unroll
            for (int ni = 0; ni < 4; ni++)
                #pragma unroll
                for (int e = 0; e < 4; e++)
                    acc[mi][ni][e] = 0.f;

        #pragma unroll
        for (int k0 = 0; k0 < KD; k0 += 16) {
            uint32_t afrag[2][4];
            #pragma unroll
            for (int mi = 0; mi < 2; mi++) {
                int r = m_base + mi * 16 + lr;
                const __nv_bfloat16* base = &Xs[r * PAD + k0 + lq * 2];
                afrag[mi][0] = *reinterpret_cast<const uint32_t*>(base);
                afrag[mi][1] = *reinterpret_cast<const uint32_t*>(base + 8 * PAD);
                afrag[mi][2] = *reinterpret_cast<const uint32_t*>(base + 8);
                afrag[mi][3] = *reinterpret_cast<const uint32_t*>(base + 8 * PAD + 8);
            }
            uint32_t bfrag[4][2];
            #pragma unroll
            for (int ni = 0; ni < 4; ni++) {
                int n = n_base + ni * 8 + lr;
                const __nv_bfloat16* base = &Ws[n * PAD + k0 + lq * 2];
                bfrag[ni][0] = *reinterpret_cast<const uint32_t*>(base);
                bfrag[ni][1] = *reinterpret_cast<const uint32_t*>(base + 8);
            }
            #pragma unroll
            for (int mi = 0; mi < 2; mi++) {
                #pragma unroll
                for (int ni = 0; ni < 4; ni++) {
                    asm volatile(
                        "mma.sync.aligned.m16n8k16.row.col.f32.bf16.bf16.f32 "
                        "{%0,%1,%2,%3}, {%4,%5,%6,%7}, {%8,%9}, {%0,%1,%2,%3};\n"
                        : "+f"(acc[mi][ni][0]), "+f"(acc[mi][ni][1]),
                          "+f"(acc[mi][ni][2]), "+f"(acc[mi][ni][3])
                        : "r"(afrag[mi][0]), "r"(afrag[mi][1]),
                          "r"(afrag[mi][2]), "r"(afrag[mi][3]),
                          "r"(bfrag[ni][0]), "r"(bfrag[ni][1]));
                }
            }
        }

        const uint32_t stage = (h == 0) ? (sb + STAGE0) : (sb + STAGE1);
        // Half-1 stage overwrites the tiles: wait until all frag reads done.
        if (h == 1) __syncthreads();

        // ---- Epilogue: 2*acc - xsq - wsq into conflict-free stage ----
        #pragma unroll
        for (int mi = 0; mi < 2; mi++) {
            int rl0 = warp_m * 32 + mi * 16 + lr;      // row local to half, 0..63
            float xs0 = xsq_s[h * 64 + rl0];
            float xs1 = xsq_s[h * 64 + rl0 + 8];
            #pragma unroll
            for (int ni = 0; ni < 4; ni++) {
                int cg = n_base + ni * 8 + lq * 2;     // col 0..127
                float ws0 = wsq_s[cg];
                float ws1 = wsq_s[cg + 1];
                sts64f(stage + (uint32_t)(rl0 * SS + cg) * 4u,
                       2.f * acc[mi][ni][0] - xs0 - ws0,
                       2.f * acc[mi][ni][1] - xs0 - ws1);
                sts64f(stage + (uint32_t)((rl0 + 8) * SS + cg) * 4u,
                       2.f * acc[mi][ni][2] - xs1 - ws0,
                       2.f * acc[mi][ni][3] - xs1 - ws1);
            }
        }
        asm volatile("fence.proxy.async.shared::cta;" ::: "memory");
        __syncthreads();

        // ---- Bulk stores: 8 warps x lanes 0-7 -> 64 rows, 512B each ----
        if (lane < 8) {
            int r = wid * 8 + lane;                    // 0..63
            const float* dst = out + (size_t)(row0 + h * 64 + r) * C + col0;
            uint32_t src = stage + (uint32_t)r * (SS * 4u);
            asm volatile("cp.async.bulk.global.shared::cta.bulk_group [%0], [%1], %2;"
                         :: "l"(dst), "r"(src), "r"(512u) : "memory");
            asm volatile("cp.async.bulk.commit_group;" ::: "memory");
        }
        // No wait for h==0: the drain overlaps the half-1 MMA.
    }

    // Drain all outstanding bulk stores before CTA exit.
    if (lane < 8)
        asm volatile("cp.async.bulk.wait_group 0;" ::: "memory");
}

extern "C" void kernel_launch(void* const* d_in, const int* in_sizes, int n_in,
                              void* d_out, int out_size) {
    const float* x = (const float*)d_in[0];
    const float* w = (const float*)d_in[1];
    float* out = (float*)d_out;
    int B = in_sizes[0] / KD;   // 32768
    int C = in_sizes[1] / KD;   // 4096

    cudaFuncSetAttribute(rbf_logits_kernel,
                         cudaFuncAttributeMaxDynamicSharedMemorySize, SMEM_BYTES);
    dim3 grid(C / BN, B / BM);  // (32, 256)
    rbf_logits_kernel<<<grid, 256, SMEM_BYTES>>>(x, w, out, C);
}